// round 9
// baseline (speedup 1.0000x reference)
#include <cuda_runtime.h>
#include <cuda_bf16.h>
#include <cstdint>

#define NN    50000
#define EE    800000
#define D     128
#define DOUTC 64
#define M_TILE 128
#define SA    136   // smem/global row stride in bf16 elements (bank-conflict-free ldmatrix)

// ---------------- scratch (no allocations allowed) ----------------
__device__ int   g_cnt[NN];            // static-zero init; re-zeroed by scan each run
__device__ int   g_row_ptr[NN + 1];
__device__ int   g_cursor[NN];
__device__ int   g_col[EE];
__device__ __align__(16) float g_B0[(size_t)NN * D];
__device__ __align__(16) float g_B1[(size_t)NN * D];
__device__ __align__(16) float g_Z [(size_t)NN * D];
// preconverted weights: 8 slots of 128 x SA bf16 (transposed, (n,k) layout)
__device__ __align__(16) __nv_bfloat16 g_Whi[8 * 128 * SA];
__device__ __align__(16) __nv_bfloat16 g_Wlo[8 * 128 * SA];

// ================= helpers =================
__device__ __forceinline__ uint32_t smem_u32(const void* p) {
    uint32_t a;
    asm("{ .reg .u64 t; cvta.to.shared.u64 t, %1; cvt.u32.u64 %0, t; }" : "=r"(a) : "l"(p));
    return a;
}

#define LDSM4(r, addr) \
    asm volatile("ldmatrix.sync.aligned.m8n8.x4.shared.b16 {%0,%1,%2,%3}, [%4];" \
        : "=r"((r)[0]), "=r"((r)[1]), "=r"((r)[2]), "=r"((r)[3]) : "r"(addr))

#define MMA_BF16(c, a, b0, b1) \
    asm volatile("mma.sync.aligned.m16n8k16.row.col.f32.bf16.bf16.f32 " \
        "{%0,%1,%2,%3}, {%4,%5,%6,%7}, {%8,%9}, {%0,%1,%2,%3};" \
        : "+f"((c)[0]), "+f"((c)[1]), "+f"((c)[2]), "+f"((c)[3]) \
        : "r"((a)[0]), "r"((a)[1]), "r"((a)[2]), "r"((a)[3]), "r"(b0), "r"(b1))

__device__ __forceinline__ void split2(float f0, float f1, uint32_t& hi, uint32_t& lo) {
    __nv_bfloat16 h0 = __float2bfloat16_rn(f0);
    __nv_bfloat16 h1 = __float2bfloat16_rn(f1);
    __nv_bfloat16 l0 = __float2bfloat16_rn(f0 - __bfloat162float(h0));
    __nv_bfloat16 l1 = __float2bfloat16_rn(f1 - __bfloat162float(h1));
    hi = (uint32_t)__bfloat16_as_ushort(h0) | ((uint32_t)__bfloat16_as_ushort(h1) << 16);
    lo = (uint32_t)__bfloat16_as_ushort(l0) | ((uint32_t)__bfloat16_as_ushort(l1) << 16);
}

// ---------------- weight preconversion: W(K x NC) -> WT hi/lo (n,k) SA layout ----------------
__global__ void prep_w_kernel(
    const float* w0, const float* w1, const float* w2, const float* w3,
    const float* w4, const float* w5, const float* w6, const float* w7)
{
    int m = blockIdx.y;
    const float* w;
    switch (m) {
        case 0: w = w0; break; case 1: w = w1; break;
        case 2: w = w2; break; case 3: w = w3; break;
        case 4: w = w4; break; case 5: w = w5; break;
        case 6: w = w6; break; default: w = w7; break;
    }
    int NC = (m == 7) ? DOUTC : 128;
    __nv_bfloat16* hi = g_Whi + m * 128 * SA;
    __nv_bfloat16* lo = g_Wlo + m * 128 * SA;
    int npairs = NC * 64;   // (n, k-pair)
    for (int idx = blockIdx.x * blockDim.x + threadIdx.x; idx < npairs;
         idx += gridDim.x * blockDim.x) {
        int n = idx % NC;
        int k = (idx / NC) * 2;
        float f0 = w[k * NC + n];
        float f1 = w[(k + 1) * NC + n];
        uint32_t h, l;
        split2(f0, f1, h, l);
        *(uint32_t*)(hi + n * SA + k) = h;
        *(uint32_t*)(lo + n * SA + k) = l;
    }
}

// ---------------- CSR build ----------------
__global__ void hist_kernel(const int* __restrict__ ei) {
    int e = blockIdx.x * blockDim.x + threadIdx.x;
    if (e < EE) {
        int d = ei[EE + e];
        if (d >= 0 && d < NN) atomicAdd(&g_cnt[d], 1);
    }
}

// single-block two-pass scan; zeroes g_cnt after consuming (next replay starts clean)
__global__ void scan_all_kernel() {
    __shared__ int wsum[32];
    const int C = 49;                 // 1024 * 49 = 50176 >= NN
    int tid = threadIdx.x;
    int lane = tid & 31, wid = tid >> 5;
    int base = tid * C;
    int s = 0;
    for (int j = 0; j < C; j++) {
        int i = base + j;
        if (i < NN) s += g_cnt[i];
    }
    int x = s;
    #pragma unroll
    for (int o = 1; o < 32; o <<= 1) {
        int t = __shfl_up_sync(0xFFFFFFFFu, x, o);
        if (lane >= o) x += t;
    }
    if (lane == 31) wsum[wid] = x;
    __syncthreads();
    if (tid < 32) {
        int y = wsum[tid];
        #pragma unroll
        for (int o = 1; o < 32; o <<= 1) {
            int t = __shfl_up_sync(0xFFFFFFFFu, y, o);
            if (tid >= o) y += t;
        }
        wsum[tid] = y;
    }
    __syncthreads();
    int incl = x + ((wid > 0) ? wsum[wid - 1] : 0);
    int run  = incl - s;              // thread-exclusive prefix
    for (int j = 0; j < C; j++) {
        int i = base + j;
        if (i < NN) {
            int v = g_cnt[i];
            g_cursor[i] = run;
            run += v;
            g_row_ptr[i + 1] = run;
            g_cnt[i] = 0;
        }
    }
    if (tid == 0) g_row_ptr[0] = 0;
}

__global__ void fill_kernel(const int* __restrict__ ei) {
    int e = blockIdx.x * blockDim.x + threadIdx.x;
    if (e < EE) {
        int d = ei[EE + e];
        int s = ei[e];
        if (d >= 0 && d < NN) {
            int pos = atomicAdd(&g_cursor[d], 1);
            g_col[pos] = s;
        }
    }
}

// ---------------- aggregation: g_Z[i] = h[i] + sum_{j->i} h[j] ----------------
__global__ __launch_bounds__(256) void agg_kernel(int src_sel, const float* __restrict__ x) {
    int warp = (blockIdx.x * blockDim.x + threadIdx.x) >> 5;
    if (warp >= NN) return;
    int lane = threadIdx.x & 31;
    const float* h = (src_sel == 0) ? x : (src_sel == 1) ? g_B0 : g_B1;
    const float4* hv = (const float4*)h;
    float4 acc = hv[(size_t)warp * 32 + lane];
    int e   = g_row_ptr[warp];
    int end = g_row_ptr[warp + 1];
    for (; e + 4 <= end; e += 4) {
        int s0 = g_col[e], s1 = g_col[e + 1], s2 = g_col[e + 2], s3 = g_col[e + 3];
        float4 v0 = hv[(size_t)s0 * 32 + lane];
        float4 v1 = hv[(size_t)s1 * 32 + lane];
        float4 v2 = hv[(size_t)s2 * 32 + lane];
        float4 v3 = hv[(size_t)s3 * 32 + lane];
        acc.x += (v0.x + v1.x) + (v2.x + v3.x);
        acc.y += (v0.y + v1.y) + (v2.y + v3.y);
        acc.z += (v0.z + v1.z) + (v2.z + v3.z);
        acc.w += (v0.w + v1.w) + (v2.w + v3.w);
    }
    for (; e < end; e++) {
        int s = g_col[e];
        float4 v = hv[(size_t)s * 32 + lane];
        acc.x += v.x; acc.y += v.y; acc.z += v.z; acc.w += v.w;
    }
    ((float4*)g_Z)[(size_t)warp * 32 + lane] = acc;
}

// ============ split-fp32 GEMM layer via mma.sync bf16 ============
// A (128 x 128) hi/lo stride SA, B' = W^T (n x k) hi/lo stride SA.
// Warp: rows [m0, m0+32), cols [n0, n0+NT*8). 3 passes AhiBhi + AhiBlo + AloBhi.
template <int NT>
__device__ __forceinline__ void gemm_layer(
    const __nv_bfloat16* Ahi, const __nv_bfloat16* Alo,
    const __nv_bfloat16* Bhi, const __nv_bfloat16* Blo,
    int m0, int n0, int lane, float c[2][NT][4])
{
    int arow = m0 + ((lane >> 3) & 1) * 8 + (lane & 7);
    int akc  = (lane >> 4) * 8;
    uint32_t aH = smem_u32(Ahi) + (uint32_t)(arow * SA + akc) * 2;
    uint32_t aL = smem_u32(Alo) + (uint32_t)(arow * SA + akc) * 2;
    int brow = (lane >> 4) * 8 + (lane & 7);
    int bkc  = ((lane >> 3) & 1) * 8;
    uint32_t bH = smem_u32(Bhi) + (uint32_t)bkc * 2;
    uint32_t bL = smem_u32(Blo) + (uint32_t)bkc * 2;

    #pragma unroll
    for (int k0 = 0; k0 < 128; k0 += 16) {
        uint32_t ah0[4], ah1[4], al0[4], al1[4];
        LDSM4(ah0, aH + k0 * 2);
        LDSM4(ah1, aH + (16 * SA + k0) * 2);
        LDSM4(al0, aL + k0 * 2);
        LDSM4(al1, aL + (16 * SA + k0) * 2);
        #pragma unroll
        for (int np = 0; np < NT / 2; np++) {
            uint32_t badd = (uint32_t)((n0 + np * 16 + brow) * SA + k0) * 2;
            uint32_t bh[4], bl[4];
            LDSM4(bh, bH + badd);
            LDSM4(bl, bL + badd);
            MMA_BF16(c[0][np * 2 + 0], ah0, bh[0], bh[1]);
            MMA_BF16(c[0][np * 2 + 0], ah0, bl[0], bl[1]);
            MMA_BF16(c[0][np * 2 + 0], al0, bh[0], bh[1]);
            MMA_BF16(c[1][np * 2 + 0], ah1, bh[0], bh[1]);
            MMA_BF16(c[1][np * 2 + 0], ah1, bl[0], bl[1]);
            MMA_BF16(c[1][np * 2 + 0], al1, bh[0], bh[1]);
            MMA_BF16(c[0][np * 2 + 1], ah0, bh[2], bh[3]);
            MMA_BF16(c[0][np * 2 + 1], ah0, bl[2], bl[3]);
            MMA_BF16(c[0][np * 2 + 1], al0, bh[2], bh[3]);
            MMA_BF16(c[1][np * 2 + 1], ah1, bh[2], bh[3]);
            MMA_BF16(c[1][np * 2 + 1], ah1, bl[2], bl[3]);
            MMA_BF16(c[1][np * 2 + 1], al1, bh[2], bh[3]);
        }
    }
}

// copy preconverted weight slot (nrows x SA bf16) into smem
__device__ __forceinline__ void stage_wcopy(
    const __nv_bfloat16* __restrict__ srcHi, const __nv_bfloat16* __restrict__ srcLo,
    __nv_bfloat16* Bhi, __nv_bfloat16* Blo, int nrows, int tid)
{
    int nvec = nrows * SA / 8;   // uint4 count
    const uint4* sh = (const uint4*)srcHi;
    const uint4* sl = (const uint4*)srcLo;
    uint4* dh = (uint4*)Bhi;
    uint4* dl = (uint4*)Blo;
    for (int i = tid; i < nvec; i += 256) { dh[i] = sh[i]; dl[i] = sl[i]; }
}

// ============ fused 2-layer MLP kernel (M_TILE=128, validated R6 geometry) ============
// layer1: 128->128 relu ; layer2: 128->N2 (+RELU2). dst_sel: 0 g_B0, 1 g_B1, 2 outp.
// Warp map: m-split x4 (m0=(wid&3)*32), n-split x2 (nIdx=wid>>2).
template <int N2, bool RELU2>
__global__ __launch_bounds__(256, 1) void mlp_mma_kernel(
    int src_sel, int dst_sel, int w1slot, int w2slot,
    const float* __restrict__ b1, const float* __restrict__ b2,
    float* __restrict__ outp)
{
    extern __shared__ __align__(16) char dyn[];
    __nv_bfloat16* Ahi = (__nv_bfloat16*)dyn;          // 128*SA
    __nv_bfloat16* Alo = Ahi + 128 * SA;
    __nv_bfloat16* Bhi = Alo + 128 * SA;
    __nv_bfloat16* Blo = Bhi + 128 * SA;
    __shared__ float sb1[128];
    __shared__ float sb2[128];

    int tid = threadIdx.x;
    int wid = tid >> 5, lane = tid & 31;
    int row0 = blockIdx.x * M_TILE;
    int m0 = (wid & 3) * 32;

    if (tid < 128) sb1[tid] = b1[tid];
    if (tid < N2)  sb2[tid] = b2[tid];

    // ---- stage A (split hi/lo) ----
    {
        const float* src = (src_sel == 0) ? g_Z : g_B0;
        const float4* sv = (const float4*)(src + (size_t)row0 * D);
        for (int i = tid; i < M_TILE * 32; i += 256) {
            int r = i >> 5, c4 = (i & 31) * 4;
            float4 v = make_float4(0.f, 0.f, 0.f, 0.f);
            if (row0 + r < NN) v = sv[i];
            uint32_t h0, l0, h1, l1;
            split2(v.x, v.y, h0, l0);
            split2(v.z, v.w, h1, l1);
            int off = r * SA + c4;
            *(uint2*)(Ahi + off) = make_uint2(h0, h1);
            *(uint2*)(Alo + off) = make_uint2(l0, l1);
        }
    }
    stage_wcopy(g_Whi + w1slot * 128 * SA, g_Wlo + w1slot * 128 * SA, Bhi, Blo, 128, tid);
    __syncthreads();

    // ---- layer 1: 128 -> 128 ----
    float c1r[2][8][4];
    #pragma unroll
    for (int a = 0; a < 2; a++)
        #pragma unroll
        for (int b = 0; b < 8; b++)
            #pragma unroll
            for (int q = 0; q < 4; q++) c1r[a][b][q] = 0.f;
    int n0 = (wid >> 2) * 64;
    gemm_layer<8>(Ahi, Alo, Bhi, Blo, m0, n0, lane, c1r);
    __syncthreads();   // all mma reads of A/B done

    // epilogue 1: bias+relu, re-split into Ahi/Alo ; then stage w2
    {
        int gid = lane >> 2, qid = lane & 3;
        #pragma unroll
        for (int mt = 0; mt < 2; mt++)
            #pragma unroll
            for (int nt = 0; nt < 8; nt++) {
                int cb = n0 + nt * 8 + qid * 2;
                int r0 = m0 + mt * 16 + gid;
                float f0 = fmaxf(c1r[mt][nt][0] + sb1[cb], 0.f);
                float f1 = fmaxf(c1r[mt][nt][1] + sb1[cb + 1], 0.f);
                uint32_t hi, lo;
                split2(f0, f1, hi, lo);
                *(uint32_t*)(Ahi + r0 * SA + cb) = hi;
                *(uint32_t*)(Alo + r0 * SA + cb) = lo;
                float f2 = fmaxf(c1r[mt][nt][2] + sb1[cb], 0.f);
                float f3 = fmaxf(c1r[mt][nt][3] + sb1[cb + 1], 0.f);
                split2(f2, f3, hi, lo);
                *(uint32_t*)(Ahi + (r0 + 8) * SA + cb) = hi;
                *(uint32_t*)(Alo + (r0 + 8) * SA + cb) = lo;
            }
    }
    stage_wcopy(g_Whi + w2slot * 128 * SA, g_Wlo + w2slot * 128 * SA, Bhi, Blo, N2, tid);
    __syncthreads();

    // ---- layer 2: 128 -> N2 ----
    constexpr int NT2 = N2 / 16;      // per-warp n-tiles (n-split across 2 warps)
    float c2r[2][NT2][4];
    #pragma unroll
    for (int a = 0; a < 2; a++)
        #pragma unroll
        for (int b = 0; b < NT2; b++)
            #pragma unroll
            for (int q = 0; q < 4; q++) c2r[a][b][q] = 0.f;
    int n02 = (wid >> 2) * (N2 / 2);
    gemm_layer<NT2>(Ahi, Alo, Bhi, Blo, m0, n02, lane, c2r);

    // epilogue 2: bias (+relu) -> global, float2 per (row, col-pair)
    {
        float* dst = (dst_sel == 0) ? g_B0 : (dst_sel == 1) ? g_B1 : outp;
        int gid = lane >> 2, qid = lane & 3;
        #pragma unroll
        for (int mt = 0; mt < 2; mt++)
            #pragma unroll
            for (int nt = 0; nt < NT2; nt++) {
                int cb = n02 + nt * 8 + qid * 2;
                int r0 = m0 + mt * 16 + gid;
                float f0 = c2r[mt][nt][0] + sb2[cb];
                float f1 = c2r[mt][nt][1] + sb2[cb + 1];
                float f2 = c2r[mt][nt][2] + sb2[cb];
                float f3 = c2r[mt][nt][3] + sb2[cb + 1];
                if (RELU2) {
                    f0 = fmaxf(f0, 0.f); f1 = fmaxf(f1, 0.f);
                    f2 = fmaxf(f2, 0.f); f3 = fmaxf(f3, 0.f);
                }
                int gr0 = row0 + r0;
                if (gr0 < NN)
                    *(float2*)(dst + (size_t)gr0 * N2 + cb) = make_float2(f0, f1);
                if (gr0 + 8 < NN)
                    *(float2*)(dst + (size_t)(gr0 + 8) * N2 + cb) = make_float2(f2, f3);
            }
    }
}

// ---------------- launch ----------------
extern "C" void kernel_launch(void* const* d_in, const int* in_sizes, int n_in,
                              void* d_out, int out_size) {
    const float* x  = (const float*)d_in[0];
    const int*   ei = (const int*)d_in[1];     // int32 (JAX x64 disabled)
    const float* c1w1 = (const float*)d_in[2];
    const float* c1b1 = (const float*)d_in[3];
    const float* c1w2 = (const float*)d_in[4];
    const float* c1b2 = (const float*)d_in[5];
    const float* c2w1 = (const float*)d_in[6];
    const float* c2b1 = (const float*)d_in[7];
    const float* c2w2 = (const float*)d_in[8];
    const float* c2b2 = (const float*)d_in[9];
    const float* c3w1 = (const float*)d_in[10];
    const float* c3b1 = (const float*)d_in[11];
    const float* c3w2 = (const float*)d_in[12];
    const float* c3b2 = (const float*)d_in[13];
    const float* l1w  = (const float*)d_in[14];
    const float* l1b  = (const float*)d_in[15];
    const float* l2w  = (const float*)d_in[16];
    const float* l2b  = (const float*)d_in[17];
    float* out = (float*)d_out;

    const int MLP_SMEM = 4 * 128 * SA * 2;   // 139264 bytes
    cudaFuncSetAttribute(mlp_mma_kernel<128, true>,
                         cudaFuncAttributeMaxDynamicSharedMemorySize, MLP_SMEM);
    cudaFuncSetAttribute(mlp_mma_kernel<64, false>,
                         cudaFuncAttributeMaxDynamicSharedMemorySize, MLP_SMEM);

    // weight preconversion (slots 0..7)
    prep_w_kernel<<<dim3(16, 8), 256>>>(c1w1, c1w2, c2w1, c2w2, c3w1, c3w2, l1w, l2w);

    // CSR build (g_cnt zeroed by previous run's scan; static zero on first run)
    hist_kernel<<<(EE + 255) / 256, 256>>>(ei);
    scan_all_kernel<<<1, 1024>>>();
    fill_kernel<<<(EE + 255) / 256, 256>>>(ei);

    const int AGG_BLOCKS = (NN * 32 + 255) / 256;
    const int TC_BLOCKS  = (NN + M_TILE - 1) / M_TILE;   // 391

    // conv1: agg(x)->Z ; mlp(Z)->B0
    agg_kernel<<<AGG_BLOCKS, 256>>>(0, x);
    mlp_mma_kernel<128, true><<<TC_BLOCKS, 256, MLP_SMEM>>>(0, 0, 0, 1, c1b1, c1b2, out);
    // conv2: agg(B0)->Z ; mlp(Z)->B1
    agg_kernel<<<AGG_BLOCKS, 256>>>(1, x);
    mlp_mma_kernel<128, true><<<TC_BLOCKS, 256, MLP_SMEM>>>(0, 1, 2, 3, c2b1, c2b2, out);
    // conv3: agg(B1)->Z ; mlp(Z)->B0
    agg_kernel<<<AGG_BLOCKS, 256>>>(2, x);
    mlp_mma_kernel<128, true><<<TC_BLOCKS, 256, MLP_SMEM>>>(0, 0, 4, 5, c3b1, c3b2, out);
    // head: B0 -> out
    mlp_mma_kernel<64, false><<<TC_BLOCKS, 256, MLP_SMEM>>>(1, 2, 6, 7, l1b, l2b, out);
}

// round 10
// speedup vs baseline: 1.2527x; 1.2527x over previous
#include <cuda_runtime.h>
#include <cuda_bf16.h>
#include <cstdint>

#define NN    50000
#define EE    800000
#define D     128
#define DOUTC 64
#define M_TILE 128
#define SA    136   // smem/global row stride in bf16 elements (bank-conflict-free ldmatrix)

// ---------------- scratch (no allocations allowed) ----------------
__device__ int   g_cnt[NN];
__device__ int   g_row_ptr[NN + 1];
__device__ int   g_cursor[NN];
__device__ int   g_col[EE];
__device__ int   g_scan[50176];
__device__ int   g_bsum[64];
__device__ int   g_boff[64];
__device__ __align__(16) float g_B0[(size_t)NN * D];
__device__ __align__(16) float g_B1[(size_t)NN * D];
__device__ __align__(16) float g_Z [(size_t)NN * D];
// preconverted weights: 8 slots of 128 x SA bf16 (transposed, (n,k) layout)
__device__ __align__(16) __nv_bfloat16 g_Whi[8 * 128 * SA];
__device__ __align__(16) __nv_bfloat16 g_Wlo[8 * 128 * SA];

// ================= helpers =================
__device__ __forceinline__ uint32_t smem_u32(const void* p) {
    uint32_t a;
    asm("{ .reg .u64 t; cvta.to.shared.u64 t, %1; cvt.u32.u64 %0, t; }" : "=r"(a) : "l"(p));
    return a;
}

#define LDSM4(r, addr) \
    asm volatile("ldmatrix.sync.aligned.m8n8.x4.shared.b16 {%0,%1,%2,%3}, [%4];" \
        : "=r"((r)[0]), "=r"((r)[1]), "=r"((r)[2]), "=r"((r)[3]) : "r"(addr))

#define MMA_BF16(c, a, b0, b1) \
    asm volatile("mma.sync.aligned.m16n8k16.row.col.f32.bf16.bf16.f32 " \
        "{%0,%1,%2,%3}, {%4,%5,%6,%7}, {%8,%9}, {%0,%1,%2,%3};" \
        : "+f"((c)[0]), "+f"((c)[1]), "+f"((c)[2]), "+f"((c)[3]) \
        : "r"((a)[0]), "r"((a)[1]), "r"((a)[2]), "r"((a)[3]), "r"(b0), "r"(b1))

__device__ __forceinline__ void split2(float f0, float f1, uint32_t& hi, uint32_t& lo) {
    __nv_bfloat16 h0 = __float2bfloat16_rn(f0);
    __nv_bfloat16 h1 = __float2bfloat16_rn(f1);
    __nv_bfloat16 l0 = __float2bfloat16_rn(f0 - __bfloat162float(h0));
    __nv_bfloat16 l1 = __float2bfloat16_rn(f1 - __bfloat162float(h1));
    hi = (uint32_t)__bfloat16_as_ushort(h0) | ((uint32_t)__bfloat16_as_ushort(h1) << 16);
    lo = (uint32_t)__bfloat16_as_ushort(l0) | ((uint32_t)__bfloat16_as_ushort(l1) << 16);
}

// ---------------- weight preconversion: W(K x NC) -> WT hi/lo (n,k) SA layout ----------------
__global__ void prep_w_kernel(
    const float* w0, const float* w1, const float* w2, const float* w3,
    const float* w4, const float* w5, const float* w6, const float* w7)
{
    int m = blockIdx.y;
    const float* w;
    switch (m) {
        case 0: w = w0; break; case 1: w = w1; break;
        case 2: w = w2; break; case 3: w = w3; break;
        case 4: w = w4; break; case 5: w = w5; break;
        case 6: w = w6; break; default: w = w7; break;
    }
    int NC = (m == 7) ? DOUTC : 128;
    __nv_bfloat16* hi = g_Whi + m * 128 * SA;
    __nv_bfloat16* lo = g_Wlo + m * 128 * SA;
    int npairs = NC * 64;   // (n, k-pair)
    for (int idx = blockIdx.x * blockDim.x + threadIdx.x; idx < npairs;
         idx += gridDim.x * blockDim.x) {
        int n = idx % NC;
        int k = (idx / NC) * 2;
        float f0 = w[k * NC + n];
        float f1 = w[(k + 1) * NC + n];
        uint32_t h, l;
        split2(f0, f1, h, l);
        *(uint32_t*)(hi + n * SA + k) = h;
        *(uint32_t*)(lo + n * SA + k) = l;
    }
}

// ---------------- CSR build (R6-validated coalesced hierarchy) ----------------
__global__ void zero_cnt_kernel() {
    int i = blockIdx.x * blockDim.x + threadIdx.x;
    if (i < NN) g_cnt[i] = 0;
}
__global__ void hist_kernel(const int* __restrict__ ei) {
    int e = blockIdx.x * blockDim.x + threadIdx.x;
    if (e < EE) {
        int d = ei[EE + e];
        if (d >= 0 && d < NN) atomicAdd(&g_cnt[d], 1);
    }
}
__global__ void scan_local_kernel() {
    __shared__ int wsum[32];
    int b = blockIdx.x, tid = threadIdx.x;
    int i = b * 1024 + tid;
    int v = (i < NN) ? g_cnt[i] : 0;
    int x = v;
    #pragma unroll
    for (int o = 1; o < 32; o <<= 1) {
        int t = __shfl_up_sync(0xFFFFFFFFu, x, o);
        if ((tid & 31) >= o) x += t;
    }
    if ((tid & 31) == 31) wsum[tid >> 5] = x;
    __syncthreads();
    if (tid < 32) {
        int s = wsum[tid];
        #pragma unroll
        for (int o = 1; o < 32; o <<= 1) {
            int t = __shfl_up_sync(0xFFFFFFFFu, s, o);
            if (tid >= o) s += t;
        }
        wsum[tid] = s;
    }
    __syncthreads();
    int incl = x + ((tid >= 32) ? wsum[(tid >> 5) - 1] : 0);
    g_scan[i] = incl;
    if (tid == 1023) g_bsum[b] = incl;
}
__global__ void scan_bsum_kernel(int nb) {
    __shared__ int w0;
    int tid = threadIdx.x;
    int v = (tid < nb) ? g_bsum[tid] : 0;
    int x = v;
    #pragma unroll
    for (int o = 1; o < 32; o <<= 1) {
        int t = __shfl_up_sync(0xFFFFFFFFu, x, o);
        if ((tid & 31) >= o) x += t;
    }
    if (tid == 31) w0 = x;
    __syncthreads();
    int incl = x + ((tid >= 32) ? w0 : 0);
    if (tid < nb) g_boff[tid] = incl - v;   // exclusive
}
__global__ void scan_final_kernel() {
    int b = blockIdx.x, tid = threadIdx.x;
    int i = b * 1024 + tid;
    if (i < NN) {
        int rp = g_scan[i] + g_boff[b];
        g_row_ptr[i + 1] = rp;
        g_cursor[i] = rp - g_cnt[i];
    }
    if (i == 0) g_row_ptr[0] = 0;
}
__global__ void fill_kernel(const int* __restrict__ ei) {
    int e = blockIdx.x * blockDim.x + threadIdx.x;
    if (e < EE) {
        int d = ei[EE + e];
        int s = ei[e];
        if (d >= 0 && d < NN) {
            int pos = atomicAdd(&g_cursor[d], 1);
            g_col[pos] = s;
        }
    }
}

// ---------------- aggregation: g_Z[i] = h[i] + sum_{j->i} h[j] ----------------
__global__ __launch_bounds__(256) void agg_kernel(int src_sel, const float* __restrict__ x) {
    int warp = (blockIdx.x * blockDim.x + threadIdx.x) >> 5;
    if (warp >= NN) return;
    int lane = threadIdx.x & 31;
    const float* h = (src_sel == 0) ? x : (src_sel == 1) ? g_B0 : g_B1;
    const float4* hv = (const float4*)h;
    float4 acc = hv[(size_t)warp * 32 + lane];
    int e   = g_row_ptr[warp];
    int end = g_row_ptr[warp + 1];
    for (; e + 4 <= end; e += 4) {
        int s0 = g_col[e], s1 = g_col[e + 1], s2 = g_col[e + 2], s3 = g_col[e + 3];
        float4 v0 = hv[(size_t)s0 * 32 + lane];
        float4 v1 = hv[(size_t)s1 * 32 + lane];
        float4 v2 = hv[(size_t)s2 * 32 + lane];
        float4 v3 = hv[(size_t)s3 * 32 + lane];
        acc.x += (v0.x + v1.x) + (v2.x + v3.x);
        acc.y += (v0.y + v1.y) + (v2.y + v3.y);
        acc.z += (v0.z + v1.z) + (v2.z + v3.z);
        acc.w += (v0.w + v1.w) + (v2.w + v3.w);
    }
    for (; e < end; e++) {
        int s = g_col[e];
        float4 v = hv[(size_t)s * 32 + lane];
        acc.x += v.x; acc.y += v.y; acc.z += v.z; acc.w += v.w;
    }
    ((float4*)g_Z)[(size_t)warp * 32 + lane] = acc;
}

// ============ split-fp32 GEMM layer via mma.sync bf16 ============
// A (128 x 128) hi/lo stride SA, B' = W^T (n x k) hi/lo stride SA.
// Warp: rows [m0, m0+32), cols [n0, n0+NT*8). 3 passes AhiBhi + AhiBlo + AloBhi.
template <int NT>
__device__ __forceinline__ void gemm_layer(
    const __nv_bfloat16* Ahi, const __nv_bfloat16* Alo,
    const __nv_bfloat16* Bhi, const __nv_bfloat16* Blo,
    int m0, int n0, int lane, float c[2][NT][4])
{
    int arow = m0 + ((lane >> 3) & 1) * 8 + (lane & 7);
    int akc  = (lane >> 4) * 8;
    uint32_t aH = smem_u32(Ahi) + (uint32_t)(arow * SA + akc) * 2;
    uint32_t aL = smem_u32(Alo) + (uint32_t)(arow * SA + akc) * 2;
    int brow = (lane >> 4) * 8 + (lane & 7);
    int bkc  = ((lane >> 3) & 1) * 8;
    uint32_t bH = smem_u32(Bhi) + (uint32_t)bkc * 2;
    uint32_t bL = smem_u32(Blo) + (uint32_t)bkc * 2;

    #pragma unroll
    for (int k0 = 0; k0 < 128; k0 += 16) {
        uint32_t ah0[4], ah1[4], al0[4], al1[4];
        LDSM4(ah0, aH + k0 * 2);
        LDSM4(ah1, aH + (16 * SA + k0) * 2);
        LDSM4(al0, aL + k0 * 2);
        LDSM4(al1, aL + (16 * SA + k0) * 2);
        #pragma unroll
        for (int np = 0; np < NT / 2; np++) {
            uint32_t badd = (uint32_t)((n0 + np * 16 + brow) * SA + k0) * 2;
            uint32_t bh[4], bl[4];
            LDSM4(bh, bH + badd);
            LDSM4(bl, bL + badd);
            MMA_BF16(c[0][np * 2 + 0], ah0, bh[0], bh[1]);
            MMA_BF16(c[0][np * 2 + 0], ah0, bl[0], bl[1]);
            MMA_BF16(c[0][np * 2 + 0], al0, bh[0], bh[1]);
            MMA_BF16(c[1][np * 2 + 0], ah1, bh[0], bh[1]);
            MMA_BF16(c[1][np * 2 + 0], ah1, bl[0], bl[1]);
            MMA_BF16(c[1][np * 2 + 0], al1, bh[0], bh[1]);
            MMA_BF16(c[0][np * 2 + 1], ah0, bh[2], bh[3]);
            MMA_BF16(c[0][np * 2 + 1], ah0, bl[2], bl[3]);
            MMA_BF16(c[0][np * 2 + 1], al0, bh[2], bh[3]);
            MMA_BF16(c[1][np * 2 + 1], ah1, bh[2], bh[3]);
            MMA_BF16(c[1][np * 2 + 1], ah1, bl[2], bl[3]);
            MMA_BF16(c[1][np * 2 + 1], al1, bh[2], bh[3]);
        }
    }
}

// copy preconverted weight slot (nrows x SA bf16) into smem
__device__ __forceinline__ void stage_wcopy(
    const __nv_bfloat16* __restrict__ srcHi, const __nv_bfloat16* __restrict__ srcLo,
    __nv_bfloat16* Bhi, __nv_bfloat16* Blo, int nrows, int tid)
{
    int nvec = nrows * SA / 8;   // uint4 count
    const uint4* sh = (const uint4*)srcHi;
    const uint4* sl = (const uint4*)srcLo;
    uint4* dh = (uint4*)Bhi;
    uint4* dl = (uint4*)Blo;
    for (int i = tid; i < nvec; i += 256) { dh[i] = sh[i]; dl[i] = sl[i]; }
}

// ============ fused 2-layer MLP kernel (M_TILE=128, validated R6 geometry) ============
// layer1: 128->128 relu ; layer2: 128->N2 (+RELU2). dst_sel: 0 g_B0, 1 g_B1, 2 outp.
// Warp map: m-split x4 (m0=(wid&3)*32), n-split x2 (nIdx=wid>>2).
template <int N2, bool RELU2>
__global__ __launch_bounds__(256, 1) void mlp_mma_kernel(
    int src_sel, int dst_sel, int w1slot, int w2slot,
    const float* __restrict__ b1, const float* __restrict__ b2,
    float* __restrict__ outp)
{
    extern __shared__ __align__(16) char dyn[];
    __nv_bfloat16* Ahi = (__nv_bfloat16*)dyn;          // 128*SA
    __nv_bfloat16* Alo = Ahi + 128 * SA;
    __nv_bfloat16* Bhi = Alo + 128 * SA;
    __nv_bfloat16* Blo = Bhi + 128 * SA;
    __shared__ float sb1[128];
    __shared__ float sb2[128];

    int tid = threadIdx.x;
    int wid = tid >> 5, lane = tid & 31;
    int row0 = blockIdx.x * M_TILE;
    int m0 = (wid & 3) * 32;

    if (tid < 128) sb1[tid] = b1[tid];
    if (tid < N2)  sb2[tid] = b2[tid];

    // ---- stage A (split hi/lo) ----
    {
        const float* src = (src_sel == 0) ? g_Z : g_B0;
        const float4* sv = (const float4*)(src + (size_t)row0 * D);
        for (int i = tid; i < M_TILE * 32; i += 256) {
            int r = i >> 5, c4 = (i & 31) * 4;
            float4 v = make_float4(0.f, 0.f, 0.f, 0.f);
            if (row0 + r < NN) v = sv[i];
            uint32_t h0, l0, h1, l1;
            split2(v.x, v.y, h0, l0);
            split2(v.z, v.w, h1, l1);
            int off = r * SA + c4;
            *(uint2*)(Ahi + off) = make_uint2(h0, h1);
            *(uint2*)(Alo + off) = make_uint2(l0, l1);
        }
    }
    stage_wcopy(g_Whi + w1slot * 128 * SA, g_Wlo + w1slot * 128 * SA, Bhi, Blo, 128, tid);
    __syncthreads();

    // ---- layer 1: 128 -> 128 ----
    float c1r[2][8][4];
    #pragma unroll
    for (int a = 0; a < 2; a++)
        #pragma unroll
        for (int b = 0; b < 8; b++)
            #pragma unroll
            for (int q = 0; q < 4; q++) c1r[a][b][q] = 0.f;
    int n0 = (wid >> 2) * 64;
    gemm_layer<8>(Ahi, Alo, Bhi, Blo, m0, n0, lane, c1r);
    __syncthreads();   // all mma reads of A/B done

    // epilogue 1: bias+relu, re-split into Ahi/Alo ; then stage w2
    {
        int gid = lane >> 2, qid = lane & 3;
        #pragma unroll
        for (int mt = 0; mt < 2; mt++)
            #pragma unroll
            for (int nt = 0; nt < 8; nt++) {
                int cb = n0 + nt * 8 + qid * 2;
                int r0 = m0 + mt * 16 + gid;
                float f0 = fmaxf(c1r[mt][nt][0] + sb1[cb], 0.f);
                float f1 = fmaxf(c1r[mt][nt][1] + sb1[cb + 1], 0.f);
                uint32_t hi, lo;
                split2(f0, f1, hi, lo);
                *(uint32_t*)(Ahi + r0 * SA + cb) = hi;
                *(uint32_t*)(Alo + r0 * SA + cb) = lo;
                float f2 = fmaxf(c1r[mt][nt][2] + sb1[cb], 0.f);
                float f3 = fmaxf(c1r[mt][nt][3] + sb1[cb + 1], 0.f);
                split2(f2, f3, hi, lo);
                *(uint32_t*)(Ahi + (r0 + 8) * SA + cb) = hi;
                *(uint32_t*)(Alo + (r0 + 8) * SA + cb) = lo;
            }
    }
    stage_wcopy(g_Whi + w2slot * 128 * SA, g_Wlo + w2slot * 128 * SA, Bhi, Blo, N2, tid);
    __syncthreads();

    // ---- layer 2: 128 -> N2 ----
    constexpr int NT2 = N2 / 16;      // per-warp n-tiles (n-split across 2 warps)
    float c2r[2][NT2][4];
    #pragma unroll
    for (int a = 0; a < 2; a++)
        #pragma unroll
        for (int b = 0; b < NT2; b++)
            #pragma unroll
            for (int q = 0; q < 4; q++) c2r[a][b][q] = 0.f;
    int n02 = (wid >> 2) * (N2 / 2);
    gemm_layer<NT2>(Ahi, Alo, Bhi, Blo, m0, n02, lane, c2r);

    // epilogue 2: bias (+relu) -> global, float2 per (row, col-pair)
    {
        float* dst = (dst_sel == 0) ? g_B0 : (dst_sel == 1) ? g_B1 : outp;
        int gid = lane >> 2, qid = lane & 3;
        #pragma unroll
        for (int mt = 0; mt < 2; mt++)
            #pragma unroll
            for (int nt = 0; nt < NT2; nt++) {
                int cb = n02 + nt * 8 + qid * 2;
                int r0 = m0 + mt * 16 + gid;
                float f0 = c2r[mt][nt][0] + sb2[cb];
                float f1 = c2r[mt][nt][1] + sb2[cb + 1];
                float f2 = c2r[mt][nt][2] + sb2[cb];
                float f3 = c2r[mt][nt][3] + sb2[cb + 1];
                if (RELU2) {
                    f0 = fmaxf(f0, 0.f); f1 = fmaxf(f1, 0.f);
                    f2 = fmaxf(f2, 0.f); f3 = fmaxf(f3, 0.f);
                }
                int gr0 = row0 + r0;
                if (gr0 < NN)
                    *(float2*)(dst + (size_t)gr0 * N2 + cb) = make_float2(f0, f1);
                if (gr0 + 8 < NN)
                    *(float2*)(dst + (size_t)(gr0 + 8) * N2 + cb) = make_float2(f2, f3);
            }
    }
}

// ---------------- launch ----------------
extern "C" void kernel_launch(void* const* d_in, const int* in_sizes, int n_in,
                              void* d_out, int out_size) {
    const float* x  = (const float*)d_in[0];
    const int*   ei = (const int*)d_in[1];     // int32 (JAX x64 disabled)
    const float* c1w1 = (const float*)d_in[2];
    const float* c1b1 = (const float*)d_in[3];
    const float* c1w2 = (const float*)d_in[4];
    const float* c1b2 = (const float*)d_in[5];
    const float* c2w1 = (const float*)d_in[6];
    const float* c2b1 = (const float*)d_in[7];
    const float* c2w2 = (const float*)d_in[8];
    const float* c2b2 = (const float*)d_in[9];
    const float* c3w1 = (const float*)d_in[10];
    const float* c3b1 = (const float*)d_in[11];
    const float* c3w2 = (const float*)d_in[12];
    const float* c3b2 = (const float*)d_in[13];
    const float* l1w  = (const float*)d_in[14];
    const float* l1b  = (const float*)d_in[15];
    const float* l2w  = (const float*)d_in[16];
    const float* l2b  = (const float*)d_in[17];
    float* out = (float*)d_out;

    const int MLP_SMEM = 4 * 128 * SA * 2;   // 139264 bytes
    cudaFuncSetAttribute(mlp_mma_kernel<128, true>,
                         cudaFuncAttributeMaxDynamicSharedMemorySize, MLP_SMEM);
    cudaFuncSetAttribute(mlp_mma_kernel<64, false>,
                         cudaFuncAttributeMaxDynamicSharedMemorySize, MLP_SMEM);

    // weight preconversion (slots 0..7)
    prep_w_kernel<<<dim3(16, 8), 256>>>(c1w1, c1w2, c2w1, c2w2, c3w1, c3w2, l1w, l2w);

    // CSR build (coalesced hierarchical scan — R6-validated)
    zero_cnt_kernel<<<(NN + 255) / 256, 256>>>();
    hist_kernel<<<(EE + 255) / 256, 256>>>(ei);
    const int SB = (NN + 1023) / 1024;   // 49
    scan_local_kernel<<<SB, 1024>>>();
    scan_bsum_kernel<<<1, 64>>>(SB);
    scan_final_kernel<<<SB, 1024>>>();
    fill_kernel<<<(EE + 255) / 256, 256>>>(ei);

    const int AGG_BLOCKS = (NN * 32 + 255) / 256;
    const int TC_BLOCKS  = (NN + M_TILE - 1) / M_TILE;   // 391

    // conv1: agg(x)->Z ; mlp(Z)->B0
    agg_kernel<<<AGG_BLOCKS, 256>>>(0, x);
    mlp_mma_kernel<128, true><<<TC_BLOCKS, 256, MLP_SMEM>>>(0, 0, 0, 1, c1b1, c1b2, out);
    // conv2: agg(B0)->Z ; mlp(Z)->B1
    agg_kernel<<<AGG_BLOCKS, 256>>>(1, x);
    mlp_mma_kernel<128, true><<<TC_BLOCKS, 256, MLP_SMEM>>>(0, 1, 2, 3, c2b1, c2b2, out);
    // conv3: agg(B1)->Z ; mlp(Z)->B0
    agg_kernel<<<AGG_BLOCKS, 256>>>(2, x);
    mlp_mma_kernel<128, true><<<TC_BLOCKS, 256, MLP_SMEM>>>(0, 0, 4, 5, c3b1, c3b2, out);
    // head: B0 -> out
    mlp_mma_kernel<64, false><<<TC_BLOCKS, 256, MLP_SMEM>>>(1, 2, 6, 7, l1b, l2b, out);
}

// round 11
// speedup vs baseline: 1.5704x; 1.2536x over previous
#include <cuda_runtime.h>
#include <cuda_bf16.h>
#include <cstdint>

#define NN    50000
#define EE    800000
#define D     128
#define DOUTC 64
#define M_TILE 128
#define NTILES ((NN + M_TILE - 1) / M_TILE)   // 391
#define SA    136   // smem row stride in bf16 elements (bank-conflict-free ldmatrix)

// ---------------- scratch (no allocations allowed) ----------------
__device__ int   g_cnt[NN];
__device__ int   g_row_ptr[NN + 1];
__device__ int   g_cursor[NN];
__device__ int   g_col[EE];
__device__ int   g_scan[50176];
__device__ int   g_bsum[64];
__device__ int   g_boff[64];
__device__ __align__(16) float g_B0[(size_t)NN * D];
__device__ __align__(16) float g_B1[(size_t)NN * D];
__device__ __align__(16) float g_Z [(size_t)NN * D];

// ================= helpers =================
__device__ __forceinline__ uint32_t smem_u32(const void* p) {
    uint32_t a;
    asm("{ .reg .u64 t; cvta.to.shared.u64 t, %1; cvt.u32.u64 %0, t; }" : "=r"(a) : "l"(p));
    return a;
}

#define LDSM4(r, addr) \
    asm volatile("ldmatrix.sync.aligned.m8n8.x4.shared.b16 {%0,%1,%2,%3}, [%4];" \
        : "=r"((r)[0]), "=r"((r)[1]), "=r"((r)[2]), "=r"((r)[3]) : "r"(addr))

#define MMA_BF16(c, a, b0, b1) \
    asm volatile("mma.sync.aligned.m16n8k16.row.col.f32.bf16.bf16.f32 " \
        "{%0,%1,%2,%3}, {%4,%5,%6,%7}, {%8,%9}, {%0,%1,%2,%3};" \
        : "+f"((c)[0]), "+f"((c)[1]), "+f"((c)[2]), "+f"((c)[3]) \
        : "r"((a)[0]), "r"((a)[1]), "r"((a)[2]), "r"((a)[3]), "r"(b0), "r"(b1))

__device__ __forceinline__ void split2(float f0, float f1, uint32_t& hi, uint32_t& lo) {
    __nv_bfloat16 h0 = __float2bfloat16_rn(f0);
    __nv_bfloat16 h1 = __float2bfloat16_rn(f1);
    __nv_bfloat16 l0 = __float2bfloat16_rn(f0 - __bfloat162float(h0));
    __nv_bfloat16 l1 = __float2bfloat16_rn(f1 - __bfloat162float(h1));
    hi = (uint32_t)__bfloat16_as_ushort(h0) | ((uint32_t)__bfloat16_as_ushort(h1) << 16);
    lo = (uint32_t)__bfloat16_as_ushort(l0) | ((uint32_t)__bfloat16_as_ushort(l1) << 16);
}

// ---------------- CSR build (R6-validated coalesced hierarchy) ----------------
__global__ void zero_cnt_kernel() {
    int i = blockIdx.x * blockDim.x + threadIdx.x;
    if (i < NN) g_cnt[i] = 0;
}
__global__ void hist_kernel(const int* __restrict__ ei) {
    int e = blockIdx.x * blockDim.x + threadIdx.x;
    if (e < EE) {
        int d = ei[EE + e];
        if (d >= 0 && d < NN) atomicAdd(&g_cnt[d], 1);
    }
}
__global__ void scan_local_kernel() {
    __shared__ int wsum[32];
    int b = blockIdx.x, tid = threadIdx.x;
    int i = b * 1024 + tid;
    int v = (i < NN) ? g_cnt[i] : 0;
    int x = v;
    #pragma unroll
    for (int o = 1; o < 32; o <<= 1) {
        int t = __shfl_up_sync(0xFFFFFFFFu, x, o);
        if ((tid & 31) >= o) x += t;
    }
    if ((tid & 31) == 31) wsum[tid >> 5] = x;
    __syncthreads();
    if (tid < 32) {
        int s = wsum[tid];
        #pragma unroll
        for (int o = 1; o < 32; o <<= 1) {
            int t = __shfl_up_sync(0xFFFFFFFFu, s, o);
            if (tid >= o) s += t;
        }
        wsum[tid] = s;
    }
    __syncthreads();
    int incl = x + ((tid >= 32) ? wsum[(tid >> 5) - 1] : 0);
    g_scan[i] = incl;
    if (tid == 1023) g_bsum[b] = incl;
}
__global__ void scan_bsum_kernel(int nb) {
    __shared__ int w0;
    int tid = threadIdx.x;
    int v = (tid < nb) ? g_bsum[tid] : 0;
    int x = v;
    #pragma unroll
    for (int o = 1; o < 32; o <<= 1) {
        int t = __shfl_up_sync(0xFFFFFFFFu, x, o);
        if ((tid & 31) >= o) x += t;
    }
    if (tid == 31) w0 = x;
    __syncthreads();
    int incl = x + ((tid >= 32) ? w0 : 0);
    if (tid < nb) g_boff[tid] = incl - v;   // exclusive
}
__global__ void scan_final_kernel() {
    int b = blockIdx.x, tid = threadIdx.x;
    int i = b * 1024 + tid;
    if (i < NN) {
        int rp = g_scan[i] + g_boff[b];
        g_row_ptr[i + 1] = rp;
        g_cursor[i] = rp - g_cnt[i];
    }
    if (i == 0) g_row_ptr[0] = 0;
}
__global__ void fill_kernel(const int* __restrict__ ei) {
    int e = blockIdx.x * blockDim.x + threadIdx.x;
    if (e < EE) {
        int d = ei[EE + e];
        int s = ei[e];
        if (d >= 0 && d < NN) {
            int pos = atomicAdd(&g_cursor[d], 1);
            g_col[pos] = s;
        }
    }
}

// ---------------- aggregation: g_Z[i] = h[i] + sum_{j->i} h[j] ----------------
__global__ __launch_bounds__(256) void agg_kernel(int src_sel, const float* __restrict__ x) {
    int warp = (blockIdx.x * blockDim.x + threadIdx.x) >> 5;
    if (warp >= NN) return;
    int lane = threadIdx.x & 31;
    const float* h = (src_sel == 0) ? x : (src_sel == 1) ? g_B0 : g_B1;
    const float4* hv = (const float4*)h;
    float4 acc = hv[(size_t)warp * 32 + lane];
    int e   = g_row_ptr[warp];
    int end = g_row_ptr[warp + 1];
    for (; e + 4 <= end; e += 4) {
        int s0 = g_col[e], s1 = g_col[e + 1], s2 = g_col[e + 2], s3 = g_col[e + 3];
        float4 v0 = hv[(size_t)s0 * 32 + lane];
        float4 v1 = hv[(size_t)s1 * 32 + lane];
        float4 v2 = hv[(size_t)s2 * 32 + lane];
        float4 v3 = hv[(size_t)s3 * 32 + lane];
        acc.x += (v0.x + v1.x) + (v2.x + v3.x);
        acc.y += (v0.y + v1.y) + (v2.y + v3.y);
        acc.z += (v0.z + v1.z) + (v2.z + v3.z);
        acc.w += (v0.w + v1.w) + (v2.w + v3.w);
    }
    for (; e < end; e++) {
        int s = g_col[e];
        float4 v = hv[(size_t)s * 32 + lane];
        acc.x += v.x; acc.y += v.y; acc.z += v.z; acc.w += v.w;
    }
    ((float4*)g_Z)[(size_t)warp * 32 + lane] = acc;
}

// ============ split-fp32 GEMM layer via mma.sync bf16 (R6-validated) ============
template <int NT>
__device__ __forceinline__ void gemm_layer(
    const __nv_bfloat16* Ahi, const __nv_bfloat16* Alo,
    const __nv_bfloat16* Bhi, const __nv_bfloat16* Blo,
    int m0, int n0, int lane, float c[2][NT][4])
{
    int arow = m0 + ((lane >> 3) & 1) * 8 + (lane & 7);
    int akc  = (lane >> 4) * 8;
    uint32_t aH = smem_u32(Ahi) + (uint32_t)(arow * SA + akc) * 2;
    uint32_t aL = smem_u32(Alo) + (uint32_t)(arow * SA + akc) * 2;
    int brow = (lane >> 4) * 8 + (lane & 7);
    int bkc  = ((lane >> 3) & 1) * 8;
    uint32_t bH = smem_u32(Bhi) + (uint32_t)bkc * 2;
    uint32_t bL = smem_u32(Blo) + (uint32_t)bkc * 2;

    #pragma unroll
    for (int k0 = 0; k0 < 128; k0 += 16) {
        uint32_t ah0[4], ah1[4], al0[4], al1[4];
        LDSM4(ah0, aH + k0 * 2);
        LDSM4(ah1, aH + (16 * SA + k0) * 2);
        LDSM4(al0, aL + k0 * 2);
        LDSM4(al1, aL + (16 * SA + k0) * 2);
        #pragma unroll
        for (int np = 0; np < NT / 2; np++) {
            uint32_t badd = (uint32_t)((n0 + np * 16 + brow) * SA + k0) * 2;
            uint32_t bh[4], bl[4];
            LDSM4(bh, bH + badd);
            LDSM4(bl, bL + badd);
            MMA_BF16(c[0][np * 2 + 0], ah0, bh[0], bh[1]);
            MMA_BF16(c[0][np * 2 + 0], ah0, bl[0], bl[1]);
            MMA_BF16(c[0][np * 2 + 0], al0, bh[0], bh[1]);
            MMA_BF16(c[1][np * 2 + 0], ah1, bh[0], bh[1]);
            MMA_BF16(c[1][np * 2 + 0], ah1, bl[0], bl[1]);
            MMA_BF16(c[1][np * 2 + 0], al1, bh[0], bh[1]);
            MMA_BF16(c[0][np * 2 + 1], ah0, bh[2], bh[3]);
            MMA_BF16(c[0][np * 2 + 1], ah0, bl[2], bl[3]);
            MMA_BF16(c[0][np * 2 + 1], al0, bh[2], bh[3]);
            MMA_BF16(c[1][np * 2 + 1], ah1, bh[2], bh[3]);
            MMA_BF16(c[1][np * 2 + 1], ah1, bl[2], bl[3]);
            MMA_BF16(c[1][np * 2 + 1], al1, bh[2], bh[3]);
        }
    }
}

// stage W (K x NC row-major, K=128) transposed+split into Bhi/Blo as (n, k) — R6-validated
__device__ __forceinline__ void stage_w(
    const float* __restrict__ w, int NC,
    __nv_bfloat16* Bhi, __nv_bfloat16* Blo, int tid)
{
    for (int i = tid; i < NC * 8; i += 256) {
        int n = i % NC, k0 = (i / NC) * 16;
        uint32_t h[8], l[8];
        #pragma unroll
        for (int j = 0; j < 8; j++) {
            float f0 = w[(k0 + 2 * j)     * NC + n];
            float f1 = w[(k0 + 2 * j + 1) * NC + n];
            split2(f0, f1, h[j], l[j]);
        }
        int off = n * SA + k0;
        *(uint4*)(Bhi + off)     = make_uint4(h[0], h[1], h[2], h[3]);
        *(uint4*)(Bhi + off + 8) = make_uint4(h[4], h[5], h[6], h[7]);
        *(uint4*)(Blo + off)     = make_uint4(l[0], l[1], l[2], l[3]);
        *(uint4*)(Blo + off + 8) = make_uint4(l[4], l[5], l[6], l[7]);
    }
}

// ============ persistent fused 2-layer MLP kernel ============
// Weights staged ONCE per CTA (w1 AND w2 up front, separate smem regions: 209KB),
// then loop over tiles. layer1: 128->128 relu ; layer2: 128->N2 (+RELU2).
// Warp map: m-split x4 (m0=(wid&3)*32), n-split x2 (nIdx=wid>>2).
template <int N2, bool RELU2>
__global__ __launch_bounds__(256, 1) void mlp_pers_kernel(
    int src_sel, int dst_sel,
    const float* __restrict__ w1, const float* __restrict__ b1,
    const float* __restrict__ w2, const float* __restrict__ b2,
    float* __restrict__ outp)
{
    extern __shared__ __align__(16) char dyn[];
    __nv_bfloat16* Ahi  = (__nv_bfloat16*)dyn;          // 128*SA
    __nv_bfloat16* Alo  = Ahi  + 128 * SA;
    __nv_bfloat16* B1hi = Alo  + 128 * SA;
    __nv_bfloat16* B1lo = B1hi + 128 * SA;
    __nv_bfloat16* B2hi = B1lo + 128 * SA;
    __nv_bfloat16* B2lo = B2hi + 128 * SA;
    __shared__ float sb1[128];
    __shared__ float sb2[128];

    int tid = threadIdx.x;
    int wid = tid >> 5, lane = tid & 31;
    int m0 = (wid & 3) * 32;

    if (tid < 128) sb1[tid] = b1[tid];
    if (tid < N2)  sb2[tid] = b2[tid];

    // stage BOTH weight matrices once
    stage_w(w1, 128, B1hi, B1lo, tid);
    stage_w(w2, N2,  B2hi, B2lo, tid);

    const float* src = (src_sel == 0) ? g_Z : g_B0;
    float* dst = (dst_sel == 0) ? g_B0 : (dst_sel == 1) ? g_B1 : outp;

    for (int tile = blockIdx.x; tile < NTILES; tile += gridDim.x) {
        int row0 = tile * M_TILE;
        __syncthreads();   // prev iter's gemm2 reads of A done; weights ready (iter 0)

        // ---- stage A (split hi/lo) ----
        {
            const float4* sv = (const float4*)(src + (size_t)row0 * D);
            for (int i = tid; i < M_TILE * 32; i += 256) {
                int r = i >> 5, c4 = (i & 31) * 4;
                float4 v = make_float4(0.f, 0.f, 0.f, 0.f);
                if (row0 + r < NN) v = sv[i];
                uint32_t h0, l0, h1, l1;
                split2(v.x, v.y, h0, l0);
                split2(v.z, v.w, h1, l1);
                int off = r * SA + c4;
                *(uint2*)(Ahi + off) = make_uint2(h0, h1);
                *(uint2*)(Alo + off) = make_uint2(l0, l1);
            }
        }
        __syncthreads();

        // ---- layer 1: 128 -> 128 ----
        float c1r[2][8][4];
        #pragma unroll
        for (int a = 0; a < 2; a++)
            #pragma unroll
            for (int b = 0; b < 8; b++)
                #pragma unroll
                for (int q = 0; q < 4; q++) c1r[a][b][q] = 0.f;
        int n0 = (wid >> 2) * 64;
        gemm_layer<8>(Ahi, Alo, B1hi, B1lo, m0, n0, lane, c1r);
        __syncthreads();   // all gemm1 reads of A done before epi1 overwrites

        // epilogue 1: bias+relu, re-split into Ahi/Alo
        {
            int gid = lane >> 2, qid = lane & 3;
            #pragma unroll
            for (int mt = 0; mt < 2; mt++)
                #pragma unroll
                for (int nt = 0; nt < 8; nt++) {
                    int cb = n0 + nt * 8 + qid * 2;
                    int r0 = m0 + mt * 16 + gid;
                    float f0 = fmaxf(c1r[mt][nt][0] + sb1[cb], 0.f);
                    float f1 = fmaxf(c1r[mt][nt][1] + sb1[cb + 1], 0.f);
                    uint32_t hi, lo;
                    split2(f0, f1, hi, lo);
                    *(uint32_t*)(Ahi + r0 * SA + cb) = hi;
                    *(uint32_t*)(Alo + r0 * SA + cb) = lo;
                    float f2 = fmaxf(c1r[mt][nt][2] + sb1[cb], 0.f);
                    float f3 = fmaxf(c1r[mt][nt][3] + sb1[cb + 1], 0.f);
                    split2(f2, f3, hi, lo);
                    *(uint32_t*)(Ahi + (r0 + 8) * SA + cb) = hi;
                    *(uint32_t*)(Alo + (r0 + 8) * SA + cb) = lo;
                }
        }
        __syncthreads();

        // ---- layer 2: 128 -> N2 ----
        constexpr int NT2 = N2 / 16;
        float c2r[2][NT2][4];
        #pragma unroll
        for (int a = 0; a < 2; a++)
            #pragma unroll
            for (int b = 0; b < NT2; b++)
                #pragma unroll
                for (int q = 0; q < 4; q++) c2r[a][b][q] = 0.f;
        int n02 = (wid >> 2) * (N2 / 2);
        gemm_layer<NT2>(Ahi, Alo, B2hi, B2lo, m0, n02, lane, c2r);

        // epilogue 2: bias (+relu) -> global
        {
            int gid = lane >> 2, qid = lane & 3;
            #pragma unroll
            for (int mt = 0; mt < 2; mt++)
                #pragma unroll
                for (int nt = 0; nt < NT2; nt++) {
                    int cb = n02 + nt * 8 + qid * 2;
                    int r0 = m0 + mt * 16 + gid;
                    float f0 = c2r[mt][nt][0] + sb2[cb];
                    float f1 = c2r[mt][nt][1] + sb2[cb + 1];
                    float f2 = c2r[mt][nt][2] + sb2[cb];
                    float f3 = c2r[mt][nt][3] + sb2[cb + 1];
                    if (RELU2) {
                        f0 = fmaxf(f0, 0.f); f1 = fmaxf(f1, 0.f);
                        f2 = fmaxf(f2, 0.f); f3 = fmaxf(f3, 0.f);
                    }
                    int gr0 = row0 + r0;
                    if (gr0 < NN)
                        *(float2*)(dst + (size_t)gr0 * N2 + cb) = make_float2(f0, f1);
                    if (gr0 + 8 < NN)
                        *(float2*)(dst + (size_t)(gr0 + 8) * N2 + cb) = make_float2(f2, f3);
                }
        }
    }
}

// ---------------- launch ----------------
extern "C" void kernel_launch(void* const* d_in, const int* in_sizes, int n_in,
                              void* d_out, int out_size) {
    const float* x  = (const float*)d_in[0];
    const int*   ei = (const int*)d_in[1];     // int32 (JAX x64 disabled)
    const float* c1w1 = (const float*)d_in[2];
    const float* c1b1 = (const float*)d_in[3];
    const float* c1w2 = (const float*)d_in[4];
    const float* c1b2 = (const float*)d_in[5];
    const float* c2w1 = (const float*)d_in[6];
    const float* c2b1 = (const float*)d_in[7];
    const float* c2w2 = (const float*)d_in[8];
    const float* c2b2 = (const float*)d_in[9];
    const float* c3w1 = (const float*)d_in[10];
    const float* c3b1 = (const float*)d_in[11];
    const float* c3w2 = (const float*)d_in[12];
    const float* c3b2 = (const float*)d_in[13];
    const float* l1w  = (const float*)d_in[14];
    const float* l1b  = (const float*)d_in[15];
    const float* l2w  = (const float*)d_in[16];
    const float* l2b  = (const float*)d_in[17];
    float* out = (float*)d_out;

    const int MLP_SMEM = 6 * 128 * SA * 2;   // 208896 bytes (A + B1 + B2, hi/lo each)
    cudaFuncSetAttribute(mlp_pers_kernel<128, true>,
                         cudaFuncAttributeMaxDynamicSharedMemorySize, MLP_SMEM);
    cudaFuncSetAttribute(mlp_pers_kernel<64, false>,
                         cudaFuncAttributeMaxDynamicSharedMemorySize, MLP_SMEM);

    // CSR build (coalesced hierarchical scan — R6-validated)
    zero_cnt_kernel<<<(NN + 255) / 256, 256>>>();
    hist_kernel<<<(EE + 255) / 256, 256>>>(ei);
    const int SB = (NN + 1023) / 1024;   // 49
    scan_local_kernel<<<SB, 1024>>>();
    scan_bsum_kernel<<<1, 64>>>(SB);
    scan_final_kernel<<<SB, 1024>>>();
    fill_kernel<<<(EE + 255) / 256, 256>>>(ei);

    const int AGG_BLOCKS = (NN * 32 + 255) / 256;
    const int PERS_BLOCKS = 148;   // one CTA per SM (persistent)

    // conv1: agg(x)->Z ; mlp(Z)->B0
    agg_kernel<<<AGG_BLOCKS, 256>>>(0, x);
    mlp_pers_kernel<128, true><<<PERS_BLOCKS, 256, MLP_SMEM>>>(0, 0, c1w1, c1b1, c1w2, c1b2, out);
    // conv2: agg(B0)->Z ; mlp(Z)->B1
    agg_kernel<<<AGG_BLOCKS, 256>>>(1, x);
    mlp_pers_kernel<128, true><<<PERS_BLOCKS, 256, MLP_SMEM>>>(0, 1, c2w1, c2b1, c2w2, c2b2, out);
    // conv3: agg(B1)->Z ; mlp(Z)->B0
    agg_kernel<<<AGG_BLOCKS, 256>>>(2, x);
    mlp_pers_kernel<128, true><<<PERS_BLOCKS, 256, MLP_SMEM>>>(0, 0, c3w1, c3b1, c3w2, c3b2, out);
    // head: B0 -> out
    mlp_pers_kernel<64, false><<<PERS_BLOCKS, 256, MLP_SMEM>>>(1, 2, l1w, l1b, l2w, l2b, out);
}